// round 1
// baseline (speedup 1.0000x reference)
#include <cuda_runtime.h>
#include <math.h>

#define KLBL 32
#define MAXB 16
#define MAXHW 409600
#define FULLMASK 0xffffffffu
#define DELTA_V 0.5f
#define TWO_DELTA_D 3.0f

// ---------------- scratch (device globals: no allocation allowed) ----------------
__device__ float g_sum[MAXB][KLBL][4];    // kernel-region segment sums
__device__ float g_cnt[MAXB][KLBL];       // per-label pixel count (tm-applied)
__device__ float g_cntk[MAXB][KLBL];      // per-label kernel-region count
__device__ float g_mean[MAXB][KLBL][4];
__device__ float g_scale[MAXB][KLBL];     // exp(max_distances)
__device__ float g_w[MAXB][KLBL];         // 1/(31*max(cnt,1)) weights for l_agg
__device__ float g_lagg[MAXB];            // accumulated l_agg per batch
__device__ float g_loss[MAXB];
__device__ unsigned char g_lab[(size_t)MAXB * MAXHW];  // tm-applied labels (6.5MB)

// ---------------- kernel 0: zero accumulators ----------------
__global__ void k_zero(int B) {
    int t = blockIdx.x * blockDim.x + threadIdx.x;
    int n1 = B * KLBL;
    if (t < n1 * 4) ((float*)g_sum)[t] = 0.f;
    if (t < n1) { ((float*)g_cnt)[t] = 0.f; ((float*)g_cntk)[t] = 0.f; }
    if (t < B) g_lagg[t] = 0.f;
}

// ---------------- kernel 1: segment sums / counts / label bytes ----------------
// Scatter into 32 bins is done with match_any + shfl subset-sums; only the group
// leader does a non-atomic RMW into a warp-private smem bin (distinct labels ->
// distinct addresses -> race free). No per-pixel shared atomics.
__global__ void __launch_bounds__(256) k_pass1(
    const float* __restrict__ emb, const int* __restrict__ inst,
    const float* __restrict__ ker, const float* __restrict__ tmk,
    int HW, int nvec)
{
    int b = blockIdx.y;
    const float4* e0 = (const float4*)(emb + ((size_t)b * 4 + 0) * HW);
    const float4* e1 = (const float4*)(emb + ((size_t)b * 4 + 1) * HW);
    const float4* e2 = (const float4*)(emb + ((size_t)b * 4 + 2) * HW);
    const float4* e3 = (const float4*)(emb + ((size_t)b * 4 + 3) * HW);
    const int4*   ip = (const int4*)(inst + (size_t)b * HW);
    const float4* kp = (const float4*)(ker + (size_t)b * HW);
    const float4* tp = (const float4*)(tmk + (size_t)b * HW);
    unsigned int* lp = (unsigned int*)(g_lab + (size_t)b * HW);

    __shared__ float s_bins[8][KLBL][6];   // per-warp bins: 4 sums, cnt, cntk
    for (int i = threadIdx.x; i < 8 * KLBL * 6; i += blockDim.x)
        ((float*)s_bins)[i] = 0.f;
    __syncthreads();

    int warp = threadIdx.x >> 5, lane = threadIdx.x & 31;
    float (*mybins)[6] = s_bins[warp];

    // nvec is a multiple of 32 (HW=409600), so warps stay uniform in this loop.
    for (int v = blockIdx.x * blockDim.x + threadIdx.x; v < nvec;
         v += gridDim.x * blockDim.x) {
        int4   iv = __ldcs(ip + v);
        float4 kv = __ldcs(kp + v);
        float4 tv = __ldcs(tp + v);
        float4 a = __ldg(e0 + v), b4 = __ldg(e1 + v);
        float4 c = __ldg(e2 + v), d4 = __ldg(e3 + v);

        float p0[4] = {a.x, a.y, a.z, a.w};
        float p1[4] = {b4.x, b4.y, b4.z, b4.w};
        float p2[4] = {c.x, c.y, c.z, c.w};
        float p3[4] = {d4.x, d4.y, d4.z, d4.w};
        int   iv4[4] = {iv.x, iv.y, iv.z, iv.w};
        float kv4[4] = {kv.x, kv.y, kv.z, kv.w};
        float tv4[4] = {tv.x, tv.y, tv.z, tv.w};

        unsigned packed = 0u;
        #pragma unroll
        for (int j = 0; j < 4; j++) {
            int L = (tv4[j] > 0.5f) ? iv4[j] : 0;
            bool kf = (kv4[j] > 0.5f);
            packed |= ((unsigned)L & 0xffu) << (8 * j);

            unsigned m  = __match_any_sync(FULLMASK, L);
            unsigned kb = __ballot_sync(FULLMASK, kf);
            unsigned mk = (L > 0) ? (m & kb) : 0u;

            float s0 = 0.f, s1 = 0.f, s2 = 0.f, s3 = 0.f;
            unsigned ii = mk;
            while (__any_sync(FULLMASK, ii != 0u)) {
                int src = ii ? (__ffs(ii) - 1) : 0;
                float t0 = __shfl_sync(FULLMASK, p0[j], src);
                float t1 = __shfl_sync(FULLMASK, p1[j], src);
                float t2 = __shfl_sync(FULLMASK, p2[j], src);
                float t3 = __shfl_sync(FULLMASK, p3[j], src);
                if (ii) { s0 += t0; s1 += t1; s2 += t2; s3 += t3; ii &= ii - 1u; }
            }
            if (L > 0 && (__ffs(m) - 1) == lane) {
                float* bp = mybins[L];
                bp[0] += s0; bp[1] += s1; bp[2] += s2; bp[3] += s3;
                bp[4] += (float)__popc(m);
                bp[5] += (float)__popc(m & kb);
            }
        }
        lp[v] = packed;
    }
    __syncthreads();

    // cross-warp reduce + one global atomic per (label, component)
    for (int i = threadIdx.x; i < KLBL * 6; i += blockDim.x) {
        int k = i / 6, comp = i % 6;
        float s = 0.f;
        #pragma unroll
        for (int w = 0; w < 8; w++) s += s_bins[w][k][comp];
        if (s != 0.f) {
            if (comp < 4)      atomicAdd(&g_sum[b][k][comp], s);
            else if (comp == 4) atomicAdd(&g_cnt[b][k], s);
            else                atomicAdd(&g_cntk[b][k], s);
        }
    }
}

// ---------------- kernel 2: means, scales, l_agg weights ----------------
__global__ void k_means(const float* __restrict__ maxd) {
    int b = blockIdx.x;
    int k = threadIdx.x;   // 32 threads
    float inv = 1.f / fmaxf(g_cntk[b][k], 1.f);
    float m0 = g_sum[b][k][0] * inv, m1 = g_sum[b][k][1] * inv;
    float m2 = g_sum[b][k][2] * inv, m3 = g_sum[b][k][3] * inv;
    if (k == 0) { m0 = m1 = m2 = m3 = 0.f; }
    g_mean[b][k][0] = m0; g_mean[b][k][1] = m1;
    g_mean[b][k][2] = m2; g_mean[b][k][3] = m3;
    g_scale[b][k] = expf(maxd[b * KLBL + k]);
    g_w[b][k] = 1.f / (31.f * fmaxf(g_cnt[b][k], 1.f));
}

// ---------------- kernel 3: l_agg (weighted single-scalar reduction) ----------------
__global__ void __launch_bounds__(256) k_pass2(
    const float* __restrict__ emb, int HW, int nvec)
{
    int b = blockIdx.y;
    __shared__ float4 s_mean[KLBL];
    __shared__ float  s_sc[KLBL];
    __shared__ float  s_w[KLBL];
    __shared__ float  s_red[8];
    if (threadIdx.x < KLBL) {
        int k = threadIdx.x;
        s_mean[k] = *(const float4*)&g_mean[b][k][0];
        s_sc[k] = g_scale[b][k];
        s_w[k]  = g_w[b][k];
    }
    __syncthreads();

    const float4* e0 = (const float4*)(emb + ((size_t)b * 4 + 0) * HW);
    const float4* e1 = (const float4*)(emb + ((size_t)b * 4 + 1) * HW);
    const float4* e2 = (const float4*)(emb + ((size_t)b * 4 + 2) * HW);
    const float4* e3 = (const float4*)(emb + ((size_t)b * 4 + 3) * HW);
    const unsigned int* lp = (const unsigned int*)(g_lab + (size_t)b * HW);

    float acc = 0.f;
    for (int v = blockIdx.x * blockDim.x + threadIdx.x; v < nvec;
         v += gridDim.x * blockDim.x) {
        unsigned lw = __ldg(lp + v);
        float4 a = __ldcs(e0 + v), b4 = __ldcs(e1 + v);
        float4 c = __ldcs(e2 + v), d4 = __ldcs(e3 + v);
        float p0[4] = {a.x, a.y, a.z, a.w};
        float p1[4] = {b4.x, b4.y, b4.z, b4.w};
        float p2[4] = {c.x, c.y, c.z, c.w};
        float p3[4] = {d4.x, d4.y, d4.z, d4.w};
        #pragma unroll
        for (int j = 0; j < 4; j++) {
            int L = (lw >> (8 * j)) & 0xff;
            if (L) {
                float4 m = s_mean[L];
                float dx = p0[j] - m.x, dy = p1[j] - m.y;
                float dz = p2[j] - m.z, dw = p3[j] - m.w;
                float d2 = fmaf(dx, dx, fmaf(dy, dy, fmaf(dz, dz, dw * dw)));
                float dist = sqrtf(d2);
                float y = fmaxf(fmaf(s_sc[L], dist, -DELTA_V), 0.f);
                acc = fmaf(__logf(fmaf(y, y, 1.f)), s_w[L], acc);
            }
        }
    }
    // block reduce
    #pragma unroll
    for (int o = 16; o > 0; o >>= 1) acc += __shfl_down_sync(FULLMASK, acc, o);
    int warp = threadIdx.x >> 5, lane = threadIdx.x & 31;
    if (lane == 0) s_red[warp] = acc;
    __syncthreads();
    if (threadIdx.x == 0) {
        float t = 0.f;
        #pragma unroll
        for (int w = 0; w < 8; w++) t += s_red[w];
        atomicAdd(&g_lagg[b], t);
    }
}

// ---------------- kernel 4: per-batch bg selection + pairs + reg + combine ----------------
__global__ void __launch_bounds__(128) k_final(const float* __restrict__ emb, int HW)
{
    int b = blockIdx.x;
    int tid = threadIdx.x, lane = tid & 31, warp = tid >> 5;
    __shared__ float4 s_mean[KLBL];
    __shared__ int s_bg[100];
    __shared__ int s_cnt;
    __shared__ int s_wc[4];
    __shared__ float s_red[4];

    if (tid < KLBL) s_mean[tid] = *(const float4*)&g_mean[b][tid][0];
    if (tid == 0) s_cnt = 0;
    __syncthreads();

    const unsigned char* lab = g_lab + (size_t)b * HW;

    // ordered scan for first 100 background (label==0) pixels; HW % 128 == 0
    for (int pass = 0; pass < 2; pass++) {
        // pass 0: background pixels; pass 1 (rare fallback): foreground fill
        if (pass == 1 && s_cnt >= 100) break;
        for (int base = 0; base < HW; base += 128) {
            int p = base + tid;
            bool f = (pass == 0) ? (lab[p] == 0) : (lab[p] != 0);
            unsigned bal = __ballot_sync(FULLMASK, f);
            if (lane == 0) s_wc[warp] = __popc(bal);
            __syncthreads();
            int before = s_cnt;
            int woff = 0;
            #pragma unroll
            for (int w = 0; w < 4; w++) if (w < warp) woff += s_wc[w];
            int total = s_wc[0] + s_wc[1] + s_wc[2] + s_wc[3];
            int rank = before + woff + __popc(bal & ((1u << lane) - 1u));
            if (f && rank < 100) s_bg[rank] = p;
            __syncthreads();
            if (tid == 0) s_cnt = before + total;
            __syncthreads();
            if (s_cnt >= 100) break;
        }
    }
    __syncthreads();

    const float coef = 1.0f - expf(-10.0f / 32.0f);

    // background term: 100 pixels x 31 means
    float acc_bg = 0.f;
    if (tid < 100) {
        int p = s_bg[tid];
        const float* eb = emb + (size_t)b * 4 * HW;
        float x0 = eb[p];
        float x1 = eb[(size_t)HW + p];
        float x2 = eb[2 * (size_t)HW + p];
        float x3 = eb[3 * (size_t)HW + p];
        #pragma unroll
        for (int k = 1; k < KLBL; k++) {
            float4 m = s_mean[k];
            float dx = x0 - m.x, dy = x1 - m.y, dz = x2 - m.z, dw = x3 - m.w;
            float dist = sqrtf(dx * dx + dy * dy + dz * dz + dw * dw);
            float y = fmaxf(fmaf(-coef, dist, TWO_DELTA_D), 0.f);
            acc_bg += logf(fmaf(y, y, 1.f));
        }
    }

    // pairwise term over labels 1..31, i != j
    float acc_pair = 0.f;
    for (int t = tid; t < 961; t += 128) {
        int i = t / 31 + 1, j = t % 31 + 1;
        if (i != j) {
            float4 mi = s_mean[i], mj = s_mean[j];
            float dx = mi.x - mj.x, dy = mi.y - mj.y;
            float dz = mi.z - mj.z, dw = mi.w - mj.w;
            float dist = sqrtf(dx * dx + dy * dy + dz * dz + dw * dw);
            float y = fmaxf(fmaf(-coef, dist, TWO_DELTA_D), 0.f);
            acc_pair += logf(fmaf(y, y, 1.f));
        }
    }

    // regularizer over all 32 labels (label 0 mean is 0 -> log(1)=0)
    float acc_reg = 0.f;
    if (tid < KLBL) {
        float4 m = s_mean[tid];
        float n = sqrtf(m.x * m.x + m.y * m.y + m.z * m.z + m.w * m.w);
        acc_reg = logf(n + 1.f);
    }

    float contrib = acc_pair * (1.f / 961.f)
                  + acc_bg * (1.f / (100.f * 961.f))
                  + acc_reg * (0.001f / 32.f);

    #pragma unroll
    for (int o = 16; o > 0; o >>= 1) contrib += __shfl_down_sync(FULLMASK, contrib, o);
    if (lane == 0) s_red[warp] = contrib;
    __syncthreads();
    if (tid == 0) {
        float t = s_red[0] + s_red[1] + s_red[2] + s_red[3];
        g_loss[b] = g_lagg[b] + t;
    }
}

// ---------------- kernel 5: mean over batches ----------------
__global__ void k_out(float* __restrict__ out, int B) {
    float s = (threadIdx.x < B) ? g_loss[threadIdx.x] : 0.f;
    #pragma unroll
    for (int o = 16; o > 0; o >>= 1) s += __shfl_down_sync(FULLMASK, s, o);
    if (threadIdx.x == 0) out[0] = s / (float)B;
}

// ---------------- launch ----------------
extern "C" void kernel_launch(void* const* d_in, const int* in_sizes, int n_in,
                              void* d_out, int out_size) {
    const float* emb  = (const float*)d_in[0];
    const int*   inst = (const int*)d_in[1];
    const float* ker  = (const float*)d_in[2];
    const float* tm   = (const float*)d_in[3];
    // d_in[4] = bboxes (unused by the loss)
    const float* maxd = (const float*)d_in[5];

    int B  = in_sizes[5] / KLBL;
    if (B < 1) B = 1;
    if (B > MAXB) B = MAXB;
    int HW = in_sizes[1] / B;
    int nvec = HW >> 2;

    k_zero<<<(B * KLBL * 4 + 255) / 256, 256>>>(B);
    dim3 g1(128, B);
    k_pass1<<<g1, 256>>>(emb, inst, ker, tm, HW, nvec);
    k_means<<<B, KLBL>>>(maxd);
    k_pass2<<<g1, 256>>>(emb, HW, nvec);
    k_final<<<B, 128>>>(emb, HW);
    k_out<<<1, 32>>>((float*)d_out, B);
}